// round 5
// baseline (speedup 1.0000x reference)
#include <cuda_runtime.h>
#include <cstddef>

// RecurrentLinearAttentionPPLM — NH=512; D=M=64; T=2048, T1=2049
// Inputs: query[NH,64], key[NH,64], value[NH,64], k_hist[NH,64,T], v_hist[NH,64,T]
// Output (flat concat): V[NH,64], K_cat[NH,64,T1], V_cat[NH,64,T1]
//
//   Qf = elu(q)+1, Kf = elu(k)+1
//   s[nh,j] = sum_d Qf[nh,d]*K_cat[nh,d,j] ;  Z = 1/(sum_j s + eps)
//   V[nh,m] = Z * sum_j s[nh,j]*V_cat[nh,m,j]

#define NH   512
#define TT   2048
#define T1   2049
#define T1P  2052
#define GRPW 8196
#define WCH  512
#define NCH  4
#define EPSF 1e-6f

__device__ float g_s [(size_t)NH * T1P];   // s row; tail (sT) at index TT
__device__ float g_zp[NH * NCH];           // per-chunk partials of sum_j s

// ---------------------------------------------------------------------------
// k_kpart: block per (nh, j-chunk of 512). Streams 64 d-rows of k_hist into
// K_cat (stride 2048 -> 2049) with aligned-body STG.128, accumulates s
// locally in registers. Chunk 3 also emits the K_cat tail column and sT.
// grid = NH*4, block = 128.
// ---------------------------------------------------------------------------
__global__ void __launch_bounds__(128) k_kpart(
    const float* __restrict__ q, const float* __restrict__ k,
    const float* __restrict__ kh, float* __restrict__ kcat)
{
    __shared__ float qf_s[64];
    __shared__ float kf_s[64];
    __shared__ __align__(16) float stage[2][WCH];
    __shared__ float red[4];

    const int b  = blockIdx.x;
    const int nh = b >> 2;
    const int c  = b & 3;
    const int j0 = c * WCH;
    const int t  = threadIdx.x;

    if (t < 64) {
        float qv = q[nh * 64 + t], kv = k[nh * 64 + t];
        qf_s[t] = qv > 0.f ? qv + 1.f : expf(qv);
        kf_s[t] = kv > 0.f ? kv + 1.f : expf(kv);
    }
    __syncthreads();

    const float* in      = kh   + (size_t)nh * 64 * TT + j0;
    float*       outbase = kcat + (size_t)nh * 64 * T1 + j0;

    float4 A = __ldcs((const float4*)in + t);
    float s0 = 0.f, s1 = 0.f, s2 = 0.f, s3 = 0.f;

    for (int d = 0; d < 64; d++) {
        float4 B;
        if (d < 63) B = __ldcs((const float4*)(in + (size_t)(d + 1) * TT) + t);

        const float qd = qf_s[d];
        s0 = fmaf(qd, A.x, s0); s1 = fmaf(qd, A.y, s1);
        s2 = fmaf(qd, A.z, s2); s3 = fmaf(qd, A.w, s3);

        float* st = stage[d & 1];
        ((float4*)st)[t] = A;
        __syncthreads();

        const int m = d & 3;          // row misalignment (words)
        const int h = (4 - m) & 3;    // head scalar count
        float* o = outbase + (size_t)d * T1;

        if (h == 0) {
            __stcs((float4*)o + t, A);
        } else {
            // neighbor quad (conflict-free LDS.128); t=127's value unused
            float4 x1 = ((const float4*)st)[(t + 1) & 127];
            float4 ov;
            if (h == 1)      ov = make_float4(A.y, A.z, A.w, x1.x);
            else if (h == 2) ov = make_float4(A.z, A.w, x1.x, x1.y);
            else             ov = make_float4(A.w, x1.x, x1.y, x1.z);
            if (t < 127) __stcs((float4*)(o + h) + t, ov);
            if (t < h)   __stcs(o + t, st[t]);                         // head
            if (t >= 8 && t < 8 + m) {                                 // tail
                const int w = h + 508 + (t - 8);
                __stcs(o + w, st[w]);
            }
        }
        A = B;
    }

    // s chunk (aligned, stays cached for k_vpart)
    ((float4*)(g_s + (size_t)nh * T1P + j0))[t] = make_float4(s0, s1, s2, s3);

    // deterministic per-chunk partial of sum_j s
    float v = s0 + s1 + s2 + s3;
    #pragma unroll
    for (int off = 16; off; off >>= 1) v += __shfl_down_sync(0xffffffffu, v, off);
    if ((t & 31) == 0) red[t >> 5] = v;
    __syncthreads();
    if (t == 0) g_zp[nh * NCH + c] = red[0] + red[1] + red[2] + red[3];

    if (c == 3) {
        if (t < 64)
            kcat[(size_t)(nh * 64 + t) * T1 + TT] = kf_s[t];  // tail column
        if (t == 0) {
            float sT = 0.f;
            #pragma unroll
            for (int d = 0; d < 64; d++) sT = fmaf(qf_s[d], kf_s[d], sT);
            g_s[(size_t)nh * T1P + TT] = sT;
        }
    }
}

// ---------------------------------------------------------------------------
// k_vpart: block per (nh, 4-m-row group); 4 rows = 8196 words = 2049 aligned
// float4s -> smem staging + contiguous STG.128 span (tails included).
// grid = NH*16, block = 256.
// ---------------------------------------------------------------------------
__global__ void __launch_bounds__(256) k_vpart(
    const float* __restrict__ vh, const float* __restrict__ val,
    float* __restrict__ vcat, float* __restrict__ vout)
{
    __shared__ float stage[GRPW];
    __shared__ float red[4][8];

    const int b  = blockIdx.x;
    const int nh = b >> 4;
    const int m0 = (b & 15) * 4;
    const int t  = threadIdx.x;
    const int warp = t >> 5, lane = t & 31;

    const size_t rowbase = (size_t)nh * 64 + m0;
    const float4* in4  = (const float4*)(vh + rowbase * TT);
    float*        outp = vcat + rowbase * T1;
    const float4* s4   = (const float4*)(g_s + (size_t)nh * T1P);

    float4 A[8];
    #pragma unroll
    for (int u = 0; u < 8; u++) A[u] = __ldcs(in4 + t + 256 * u);

    const float4 sa = s4[t];
    const float4 sb = s4[256 + t];

    float acc[4] = {0.f, 0.f, 0.f, 0.f};
    #pragma unroll
    for (int u = 0; u < 8; u++) {
        const int r = u >> 1;
        const float4 sv = (u & 1) ? sb : sa;
        float4 a = A[u];
        acc[r] = fmaf(sv.x, a.x, acc[r]);
        acc[r] = fmaf(sv.y, a.y, acc[r]);
        acc[r] = fmaf(sv.z, a.z, acc[r]);
        acc[r] = fmaf(sv.w, a.w, acc[r]);
        const int x = r * T1 + 4 * t + (u & 1) * 1024;
        stage[x] = a.x; stage[x + 1] = a.y; stage[x + 2] = a.z; stage[x + 3] = a.w;
    }
    if (t < 4) stage[t * T1 + TT] = val[rowbase + t];   // V_cat tail column

    #pragma unroll
    for (int r = 0; r < 4; r++) {
        float v = acc[r];
        #pragma unroll
        for (int off = 16; off; off >>= 1) v += __shfl_down_sync(0xffffffffu, v, off);
        if (lane == 0) red[r][warp] = v;
    }
    __syncthreads();

    float4*       o4  = (float4*)outp;
    const float4* st4 = (const float4*)stage;
    #pragma unroll
    for (int u = 0; u < 8; u++) __stcs(o4 + t + 256 * u, st4[t + 256 * u]);
    if (t == 0) __stcs(o4 + 2048, st4[2048]);

    if (t < 4) {
        float tot = 0.f;
        #pragma unroll
        for (int w = 0; w < 8; w++) tot += red[t][w];
        const float sT    = g_s[(size_t)nh * T1P + TT];
        const float vlast = val[rowbase + t];
        const float zsum  = g_zp[nh * NCH + 0] + g_zp[nh * NCH + 1]
                          + g_zp[nh * NCH + 2] + g_zp[nh * NCH + 3] + sT;
        vout[rowbase + t] = (tot + sT * vlast) / (zsum + EPSF);
    }
}

// ---------------------------------------------------------------------------
extern "C" void kernel_launch(void* const* d_in, const int* in_sizes, int n_in,
                              void* d_out, int out_size)
{
    const float* q   = (const float*)d_in[0];
    const float* k   = (const float*)d_in[1];
    const float* val = (const float*)d_in[2];
    const float* kh  = (const float*)d_in[3];
    const float* vh  = (const float*)d_in[4];

    float* out  = (float*)d_out;
    float* vout = out;
    float* kcat = out + (size_t)NH * 64;
    float* vcat = kcat + (size_t)NH * 64 * T1;

    k_kpart<<<NH * NCH, 128>>>(q, k, kh, kcat);
    k_vpart<<<NH * 16, 256>>>(vh, val, vcat, vout);
}